// round 1
// baseline (speedup 1.0000x reference)
#include <cuda_runtime.h>
#include <math.h>

#define B_   4
#define S_   2048
#define H_   1024
#define NH_  16
#define HD_  64
#define MTOT (B_ * S_)   // 8192

// ---------------- scratch (no allocs allowed) ----------------
__device__ float g_q[(size_t)B_ * NH_ * S_ * HD_];    // [B,NH,S,HD]
__device__ float g_k[(size_t)B_ * NH_ * S_ * HD_];
__device__ float g_v[(size_t)B_ * NH_ * S_ * HD_];
__device__ float g_ctx[(size_t)B_ * S_ * H_];         // [B,S,H]
__device__ float g_h[(size_t)B_ * S_ * H_];           // pre-LN

// ---------------- tiled NT GEMM: C[M,N] = A[M,K] * W[N,K]^T + bias ----------
// qkv_layout=1: write to [B,NH,S,HD] scratch.  qkv_layout=0: row-major + resid.
#define GBM 128
#define GBN 128
#define GBK 8

__global__ __launch_bounds__(256) void gemm_nt(
    const float* __restrict__ A, const float* __restrict__ W,
    const float* __restrict__ bias, const float* __restrict__ resid,
    float* __restrict__ C, int M, int N, int K, int qkv_layout)
{
    __shared__ float As[GBK][GBM];
    __shared__ float Bs[GBK][GBN];

    const int tid = threadIdx.x;
    const int tx = tid & 15;        // 0..15 (cols)
    const int ty = tid >> 4;        // 0..15 (rows)
    const int rowBase = blockIdx.y * GBM;
    const int colBase = blockIdx.x * GBN;

    float acc[8][8];
#pragma unroll
    for (int i = 0; i < 8; i++)
#pragma unroll
        for (int j = 0; j < 8; j++) acc[i][j] = 0.f;

    const int lr = tid >> 1;          // 0..127
    const int lc = (tid & 1) * 4;     // 0 or 4

    const float* Aptr = A + (size_t)(rowBase + lr) * K + lc;
    const float* Wptr = W + (size_t)(colBase + lr) * K + lc;

    for (int kt = 0; kt < K; kt += GBK) {
        float4 av = *(const float4*)(Aptr + kt);
        float4 bv = *(const float4*)(Wptr + kt);
        As[lc + 0][lr] = av.x; As[lc + 1][lr] = av.y;
        As[lc + 2][lr] = av.z; As[lc + 3][lr] = av.w;
        Bs[lc + 0][lr] = bv.x; Bs[lc + 1][lr] = bv.y;
        Bs[lc + 2][lr] = bv.z; Bs[lc + 3][lr] = bv.w;
        __syncthreads();

#pragma unroll
        for (int k = 0; k < GBK; k++) {
            float a[8], b[8];
            *(float4*)&a[0] = *(const float4*)&As[k][ty * 8];
            *(float4*)&a[4] = *(const float4*)&As[k][ty * 8 + 4];
            *(float4*)&b[0] = *(const float4*)&Bs[k][tx * 8];
            *(float4*)&b[4] = *(const float4*)&Bs[k][tx * 8 + 4];
#pragma unroll
            for (int i = 0; i < 8; i++)
#pragma unroll
                for (int j = 0; j < 8; j++)
                    acc[i][j] += a[i] * b[j];
        }
        __syncthreads();
    }

    if (qkv_layout) {
#pragma unroll
        for (int i = 0; i < 8; i++) {
            int m = rowBase + ty * 8 + i;
            int bb = m >> 11, ss = m & (S_ - 1);
#pragma unroll
            for (int j = 0; j < 8; j++) {
                int n = colBase + tx * 8 + j;
                int h = n >> 6, d = n & (HD_ - 1);
                C[((((size_t)bb * NH_) + h) * S_ + ss) * HD_ + d] =
                    acc[i][j] + bias[n];
            }
        }
    } else {
#pragma unroll
        for (int i = 0; i < 8; i++) {
            int m = rowBase + ty * 8 + i;
#pragma unroll
            for (int j = 0; j < 8; j++) {
                int n = colBase + tx * 8 + j;
                C[(size_t)m * N + n] = acc[i][j] + bias[n] + resid[(size_t)m * N + n];
            }
        }
    }
}

// ---------------- flash attention: 1 query per thread --------------------
#define BQ  128
#define BKV 16

__global__ __launch_bounds__(128) void flash_attn(
    const float* __restrict__ Q, const float* __restrict__ Kt,
    const float* __restrict__ V, float* __restrict__ ctx)
{
    __shared__ float Ks[BKV][HD_];
    __shared__ float Vs[BKV][HD_];

    const int b = blockIdx.z;
    const int h = blockIdx.y;
    const int q0 = blockIdx.x * BQ + threadIdx.x;

    const size_t headBase = (((size_t)b * NH_ + h) * S_) * HD_;
    const float* qptr  = Q  + headBase + (size_t)q0 * HD_;
    const float* kbase = Kt + headBase;
    const float* vbase = V  + headBase;

    float qreg[HD_];
#pragma unroll
    for (int d = 0; d < HD_; d++) qreg[d] = qptr[d];

    float o[HD_];
#pragma unroll
    for (int d = 0; d < HD_; d++) o[d] = 0.f;
    float mrun = -1e30f, lrun = 0.f;
    const float scale = 0.125f;   // 1/sqrt(64)

    for (int j0 = 0; j0 < S_; j0 += BKV) {
        {
            const int t = threadIdx.x;
            const float4* ks = (const float4*)(kbase + (size_t)j0 * HD_);
            const float4* vs = (const float4*)(vbase + (size_t)j0 * HD_);
            float4* kd = (float4*)&Ks[0][0];
            float4* vd = (float4*)&Vs[0][0];
            kd[t] = ks[t]; kd[t + 128] = ks[t + 128];
            vd[t] = vs[t]; vd[t + 128] = vs[t + 128];
        }
        __syncthreads();

        float s[BKV];
#pragma unroll
        for (int jj = 0; jj < BKV; jj++) s[jj] = 0.f;
#pragma unroll
        for (int d = 0; d < HD_; d++) {
            float qd = qreg[d];
#pragma unroll
            for (int jj = 0; jj < BKV; jj++)
                s[jj] += qd * Ks[jj][d];
        }

        float mt = mrun;
#pragma unroll
        for (int jj = 0; jj < BKV; jj++) {
            s[jj] *= scale;
            mt = fmaxf(mt, s[jj]);
        }
        float corr = __expf(mrun - mt);
        lrun *= corr;
#pragma unroll
        for (int d = 0; d < HD_; d++) o[d] *= corr;

#pragma unroll
        for (int jj = 0; jj < BKV; jj++) {
            float p = __expf(s[jj] - mt);
            lrun += p;
#pragma unroll
            for (int d = 0; d < HD_; d++)
                o[d] += p * Vs[jj][d];
        }
        mrun = mt;
        __syncthreads();
    }

    float inv = 1.0f / lrun;
    float* optr = ctx + ((size_t)b * S_ + q0) * H_ + h * HD_;
#pragma unroll
    for (int d = 0; d < HD_; d += 4) {
        float4 v4 = make_float4(o[d] * inv, o[d + 1] * inv,
                                o[d + 2] * inv, o[d + 3] * inv);
        *(float4*)(optr + d) = v4;
    }
}

// ---------------- layernorm (one block per row) --------------------------
__global__ __launch_bounds__(256) void layernorm_k(
    const float* __restrict__ hin, const float* __restrict__ gamma,
    const float* __restrict__ beta, float* __restrict__ out)
{
    const int row = blockIdx.x;
    const int t = threadIdx.x;
    const float* hp = hin + (size_t)row * H_;
    float* op = out + (size_t)row * H_;

    float4 x4 = ((const float4*)hp)[t];
    float sum = x4.x + x4.y + x4.z + x4.w;
    float sq  = x4.x * x4.x + x4.y * x4.y + x4.z * x4.z + x4.w * x4.w;

#pragma unroll
    for (int off = 16; off > 0; off >>= 1) {
        sum += __shfl_xor_sync(0xFFFFFFFFu, sum, off);
        sq  += __shfl_xor_sync(0xFFFFFFFFu, sq,  off);
    }
    __shared__ float ssum[8], ssq[8];
    const int wid = t >> 5, lid = t & 31;
    if (lid == 0) { ssum[wid] = sum; ssq[wid] = sq; }
    __syncthreads();
    if (wid == 0) {
        float a = (lid < 8) ? ssum[lid] : 0.f;
        float b = (lid < 8) ? ssq[lid]  : 0.f;
#pragma unroll
        for (int off = 4; off > 0; off >>= 1) {
            a += __shfl_xor_sync(0xFFFFFFFFu, a, off);
            b += __shfl_xor_sync(0xFFFFFFFFu, b, off);
        }
        if (lid == 0) { ssum[0] = a; ssq[0] = b; }
    }
    __syncthreads();
    const float mean = ssum[0] * (1.0f / H_);
    const float var  = ssq[0] * (1.0f / H_) - mean * mean;
    const float rstd = rsqrtf(var + 1e-12f);

    float4 g4 = ((const float4*)gamma)[t];
    float4 b4 = ((const float4*)beta)[t];
    float4 o4;
    o4.x = g4.x * (x4.x - mean) * rstd + b4.x;
    o4.y = g4.y * (x4.y - mean) * rstd + b4.y;
    o4.z = g4.z * (x4.z - mean) * rstd + b4.z;
    o4.w = g4.w * (x4.w - mean) * rstd + b4.w;
    ((float4*)op)[t] = o4;
}

// ---------------- launch ----------------
extern "C" void kernel_launch(void* const* d_in, const int* in_sizes, int n_in,
                              void* d_out, int out_size)
{
    const float* x     = (const float*)d_in[0];
    const float* wq    = (const float*)d_in[1];
    const float* bq    = (const float*)d_in[2];
    const float* wk    = (const float*)d_in[3];
    const float* bk    = (const float*)d_in[4];
    const float* wv    = (const float*)d_in[5];
    const float* bv    = (const float*)d_in[6];
    const float* wo    = (const float*)d_in[7];
    const float* bo    = (const float*)d_in[8];
    const float* gamma = (const float*)d_in[9];
    const float* beta  = (const float*)d_in[10];

    float *q, *k, *v, *ctx, *hbuf;
    cudaGetSymbolAddress((void**)&q,    g_q);
    cudaGetSymbolAddress((void**)&k,    g_k);
    cudaGetSymbolAddress((void**)&v,    g_v);
    cudaGetSymbolAddress((void**)&ctx,  g_ctx);
    cudaGetSymbolAddress((void**)&hbuf, g_h);

    dim3 gb(H_ / GBN, MTOT / GBM);   // (8, 64)
    dim3 tb(256);

    gemm_nt<<<gb, tb>>>(x, wq, bq, nullptr, q, MTOT, H_, H_, 1);
    gemm_nt<<<gb, tb>>>(x, wk, bk, nullptr, k, MTOT, H_, H_, 1);
    gemm_nt<<<gb, tb>>>(x, wv, bv, nullptr, v, MTOT, H_, H_, 1);

    flash_attn<<<dim3(S_ / BQ, NH_, B_), 128>>>(q, k, v, ctx);

    gemm_nt<<<gb, tb>>>(ctx, wo, bo, x, hbuf, MTOT, H_, H_, 0);

    layernorm_k<<<MTOT, 256>>>(hbuf, gamma, beta, (float*)d_out);
}

// round 2
// speedup vs baseline: 1.2392x; 1.2392x over previous
#include <cuda_runtime.h>
#include <cuda_bf16.h>
#include <math.h>
#include <stdint.h>

#define B_   4
#define S_   2048
#define H_   1024
#define NH_  16
#define HD_  64
#define MTOT (B_ * S_)   // 8192

// ---------------- scratch (no allocs allowed) ----------------
__device__ float g_q[(size_t)B_ * NH_ * S_ * HD_];    // [B,NH,S,HD]
__device__ float g_k[(size_t)B_ * NH_ * S_ * HD_];
__device__ float g_v[(size_t)B_ * NH_ * S_ * HD_];
__device__ float g_ctx[(size_t)B_ * S_ * H_];         // [B,S,H]
__device__ float g_h[(size_t)B_ * S_ * H_];           // pre-LN

// ============================================================
//  bf16x3 tensor-core GEMM:  C[M,N] = A[M,K] * W[N,K]^T + bias
//  fp32 emulated via hi/lo bf16 split (3 MMAs per tile-pair)
// ============================================================
#define BM 128
#define BN 128
#define BK 32
#define LDS_PAD 8           // row stride = BK+8 = 40 halves (conflict-free ldsm)
#define LDK (BK + LDS_PAD)

__device__ __forceinline__ void mma16816(float* c, const uint32_t* a, const uint32_t* b) {
    asm volatile(
        "mma.sync.aligned.m16n8k16.row.col.f32.bf16.bf16.f32 "
        "{%0,%1,%2,%3}, {%4,%5,%6,%7}, {%8,%9}, {%0,%1,%2,%3};\n"
        : "+f"(c[0]), "+f"(c[1]), "+f"(c[2]), "+f"(c[3])
        : "r"(a[0]), "r"(a[1]), "r"(a[2]), "r"(a[3]), "r"(b[0]), "r"(b[1]));
}

__device__ __forceinline__ void ldsm_x4(uint32_t* r, uint32_t addr) {
    asm volatile(
        "ldmatrix.sync.aligned.m8n8.x4.shared.b16 {%0,%1,%2,%3}, [%4];\n"
        : "=r"(r[0]), "=r"(r[1]), "=r"(r[2]), "=r"(r[3]) : "r"(addr));
}

__global__ __launch_bounds__(256) void gemm_bf16x3(
    const float* __restrict__ A, const float* __restrict__ W,
    const float* __restrict__ bias, const float* __restrict__ resid,
    float* __restrict__ C, int qkv_layout)
{
    const int K = H_, N = H_;
    __shared__ __nv_bfloat16 Ah[BM][LDK], Al[BM][LDK];
    __shared__ __nv_bfloat16 Bh[BN][LDK], Bl[BN][LDK];

    const int tid  = threadIdx.x;
    const int warp = tid >> 5;
    const int lane = tid & 31;
    const int rowBase = blockIdx.y * BM;
    const int colBase = blockIdx.x * BN;

    const int m0 = (warp >> 1) * 32;   // warp grid 4(m) x 2(n)
    const int n0 = (warp & 1) * 64;

    // gmem load assignment: row = tid>>1 (0..127), col half = (tid&1)*16
    const int lrow = tid >> 1;
    const int lcol = (tid & 1) * 16;
    const float* Ag = A + (size_t)(rowBase + lrow) * K + lcol;
    const float* Wg = W + (size_t)(colBase + lrow) * K + lcol;

    // ldmatrix lane addresses (element offsets within padded smem tiles)
    const int a_row = m0 + ((lane >> 3) & 1) * 8 + (lane & 7);
    const int a_col = ((lane >> 4) & 1) * 8;
    const int b_row = n0 + ((lane >> 4) & 1) * 8 + (lane & 7);
    const int b_col = ((lane >> 3) & 1) * 8;

    const uint32_t sAh = (uint32_t)__cvta_generic_to_shared(&Ah[0][0]);
    const uint32_t sAl = (uint32_t)__cvta_generic_to_shared(&Al[0][0]);
    const uint32_t sBh = (uint32_t)__cvta_generic_to_shared(&Bh[0][0]);
    const uint32_t sBl = (uint32_t)__cvta_generic_to_shared(&Bl[0][0]);

    float acc[2][8][4];
#pragma unroll
    for (int i = 0; i < 2; i++)
#pragma unroll
        for (int j = 0; j < 8; j++)
#pragma unroll
            for (int r = 0; r < 4; r++) acc[i][j][r] = 0.f;

    float4 ra[4], rb[4];
    // prologue: fetch tile 0
#pragma unroll
    for (int v = 0; v < 4; v++) {
        ra[v] = *(const float4*)(Ag + v * 4);
        rb[v] = *(const float4*)(Wg + v * 4);
    }

    for (int kt = 0; kt < K; kt += BK) {
        // convert + store regs -> smem
#pragma unroll
        for (int v = 0; v < 4; v++) {
            const float* fa = (const float*)&ra[v];
            const float* fb = (const float*)&rb[v];
#pragma unroll
            for (int e = 0; e < 4; e++) {
                int c = lcol + v * 4 + e;
                __nv_bfloat16 h = __float2bfloat16(fa[e]);
                Ah[lrow][c] = h;
                Al[lrow][c] = __float2bfloat16(fa[e] - __bfloat162float(h));
                __nv_bfloat16 g = __float2bfloat16(fb[e]);
                Bh[lrow][c] = g;
                Bl[lrow][c] = __float2bfloat16(fb[e] - __bfloat162float(g));
            }
        }
        __syncthreads();

        // prefetch next tile (LDGs in flight during compute)
        if (kt + BK < K) {
#pragma unroll
            for (int v = 0; v < 4; v++) {
                ra[v] = *(const float4*)(Ag + kt + BK + v * 4);
                rb[v] = *(const float4*)(Wg + kt + BK + v * 4);
            }
        }

#pragma unroll
        for (int ks = 0; ks < 2; ks++) {   // two k16 steps per BK=32
            const int kb = ks * 16;
            uint32_t ah[2][4], al[2][4], bh[8][2], bl[8][2];
#pragma unroll
            for (int mi = 0; mi < 2; mi++) {
                uint32_t off = (uint32_t)(((a_row + mi * 16) * LDK) + kb + a_col) * 2;
                ldsm_x4(ah[mi], sAh + off);
                ldsm_x4(al[mi], sAl + off);
            }
#pragma unroll
            for (int p = 0; p < 4; p++) {
                uint32_t off = (uint32_t)(((b_row + p * 16) * LDK) + kb + b_col) * 2;
                uint32_t t[4];
                ldsm_x4(t, sBh + off);
                bh[2 * p][0] = t[0]; bh[2 * p][1] = t[1];
                bh[2 * p + 1][0] = t[2]; bh[2 * p + 1][1] = t[3];
                ldsm_x4(t, sBl + off);
                bl[2 * p][0] = t[0]; bl[2 * p][1] = t[1];
                bl[2 * p + 1][0] = t[2]; bl[2 * p + 1][1] = t[3];
            }
#pragma unroll
            for (int nj = 0; nj < 8; nj++)
#pragma unroll
                for (int mi = 0; mi < 2; mi++) {
                    mma16816(acc[mi][nj], ah[mi], bh[nj]);
                    mma16816(acc[mi][nj], ah[mi], bl[nj]);
                    mma16816(acc[mi][nj], al[mi], bh[nj]);
                }
        }
        __syncthreads();
    }

    // -------- epilogue --------
    const int g  = lane >> 2;
    const int t2 = (lane & 3) * 2;
#pragma unroll
    for (int mi = 0; mi < 2; mi++) {
#pragma unroll
        for (int nj = 0; nj < 8; nj++) {
            int n = colBase + n0 + nj * 8 + t2;
            float bia0 = bias[n], bia1 = bias[n + 1];
#pragma unroll
            for (int rr = 0; rr < 2; rr++) {
                int m = rowBase + m0 + mi * 16 + g + rr * 8;
                float v0 = acc[mi][nj][rr * 2 + 0] + bia0;
                float v1 = acc[mi][nj][rr * 2 + 1] + bia1;
                if (qkv_layout) {
                    int bb = m >> 11, ss = m & (S_ - 1);
                    int hh = n >> 6, dd = n & (HD_ - 1);
                    float2* dst = (float2*)&C[((((size_t)bb * NH_) + hh) * S_ + ss) * HD_ + dd];
                    *dst = make_float2(v0, v1);
                } else {
                    const float2 rs = *(const float2*)&resid[(size_t)m * N + n];
                    *(float2*)&C[(size_t)m * N + n] = make_float2(v0 + rs.x, v1 + rs.y);
                }
            }
        }
    }
}

// ============================================================
//  flash attention: 2 threads per query (half head-dim each)
// ============================================================
#define BQ  128   // queries per block
#define BKV 16

__global__ __launch_bounds__(256) void flash_attn2(
    const float* __restrict__ Q, const float* __restrict__ Kt,
    const float* __restrict__ V, float* __restrict__ ctx)
{
    __shared__ float Ks[BKV][HD_];
    __shared__ float Vs[BKV][HD_];

    const int b = blockIdx.z;
    const int h = blockIdx.y;
    const int tid  = threadIdx.x;
    const int wid  = tid >> 5;
    const int lane = tid & 31;
    const int qi    = wid * 16 + (lane & 15);      // 0..127
    const int dhalf = lane >> 4;                   // 0 or 1
    const int dbase = dhalf * 32;
    const int q0 = blockIdx.x * BQ + qi;

    const size_t headBase = (((size_t)b * NH_ + h) * S_) * HD_;
    const float* qptr  = Q  + headBase + (size_t)q0 * HD_ + dbase;
    const float* kbase = Kt + headBase;
    const float* vbase = V  + headBase;

    float qreg[32];
#pragma unroll
    for (int d = 0; d < 32; d++) qreg[d] = qptr[d];

    float o[32];
#pragma unroll
    for (int d = 0; d < 32; d++) o[d] = 0.f;
    float mrun = -1e30f, lrun = 0.f;
    const float scale = 0.125f;   // 1/sqrt(64)

    for (int j0 = 0; j0 < S_; j0 += BKV) {
        {
            const float4* ks = (const float4*)(kbase + (size_t)j0 * HD_);
            const float4* vs = (const float4*)(vbase + (size_t)j0 * HD_);
            ((float4*)&Ks[0][0])[tid] = ks[tid];
            ((float4*)&Vs[0][0])[tid] = vs[tid];
        }
        __syncthreads();

        float s[BKV];
#pragma unroll
        for (int jj = 0; jj < BKV; jj++) s[jj] = 0.f;
#pragma unroll
        for (int d = 0; d < 32; d++) {
            float qd = qreg[d];
#pragma unroll
            for (int jj = 0; jj < BKV; jj++)
                s[jj] += qd * Ks[jj][dbase + d];
        }
        // combine the two half-dim partials (lanes l <-> l^16)
#pragma unroll
        for (int jj = 0; jj < BKV; jj++)
            s[jj] += __shfl_xor_sync(0xFFFFFFFFu, s[jj], 16);

        float mt = mrun;
#pragma unroll
        for (int jj = 0; jj < BKV; jj++) {
            s[jj] *= scale;
            mt = fmaxf(mt, s[jj]);
        }
        float corr = __expf(mrun - mt);
        lrun *= corr;
#pragma unroll
        for (int d = 0; d < 32; d++) o[d] *= corr;

#pragma unroll
        for (int jj = 0; jj < BKV; jj++) {
            float p = __expf(s[jj] - mt);
            lrun += p;
#pragma unroll
            for (int d = 0; d < 32; d++)
                o[d] += p * Vs[jj][dbase + d];
        }
        mrun = mt;
        __syncthreads();
    }

    float inv = 1.0f / lrun;
    float* optr = ctx + ((size_t)b * S_ + q0) * H_ + h * HD_ + dbase;
#pragma unroll
    for (int d = 0; d < 32; d += 4) {
        *(float4*)(optr + d) = make_float4(o[d] * inv, o[d + 1] * inv,
                                           o[d + 2] * inv, o[d + 3] * inv);
    }
}

// ---------------- layernorm (one block per row) --------------------------
__global__ __launch_bounds__(256) void layernorm_k(
    const float* __restrict__ hin, const float* __restrict__ gamma,
    const float* __restrict__ beta, float* __restrict__ out)
{
    const int row = blockIdx.x;
    const int t = threadIdx.x;
    const float* hp = hin + (size_t)row * H_;
    float* op = out + (size_t)row * H_;

    float4 x4 = ((const float4*)hp)[t];
    float sum = x4.x + x4.y + x4.z + x4.w;
    float sq  = x4.x * x4.x + x4.y * x4.y + x4.z * x4.z + x4.w * x4.w;

#pragma unroll
    for (int off = 16; off > 0; off >>= 1) {
        sum += __shfl_xor_sync(0xFFFFFFFFu, sum, off);
        sq  += __shfl_xor_sync(0xFFFFFFFFu, sq,  off);
    }
    __shared__ float ssum[8], ssq[8];
    const int wid = t >> 5, lid = t & 31;
    if (lid == 0) { ssum[wid] = sum; ssq[wid] = sq; }
    __syncthreads();
    if (wid == 0) {
        float a = (lid < 8) ? ssum[lid] : 0.f;
        float b = (lid < 8) ? ssq[lid]  : 0.f;
#pragma unroll
        for (int off = 4; off > 0; off >>= 1) {
            a += __shfl_xor_sync(0xFFFFFFFFu, a, off);
            b += __shfl_xor_sync(0xFFFFFFFFu, b, off);
        }
        if (lid == 0) { ssum[0] = a; ssq[0] = b; }
    }
    __syncthreads();
    const float mean = ssum[0] * (1.0f / H_);
    const float var  = ssq[0] * (1.0f / H_) - mean * mean;
    const float rstd = rsqrtf(var + 1e-12f);

    float4 g4 = ((const float4*)gamma)[t];
    float4 b4 = ((const float4*)beta)[t];
    float4 o4;
    o4.x = g4.x * (x4.x - mean) * rstd + b4.x;
    o4.y = g4.y * (x4.y - mean) * rstd + b4.y;
    o4.z = g4.z * (x4.z - mean) * rstd + b4.z;
    o4.w = g4.w * (x4.w - mean) * rstd + b4.w;
    ((float4*)op)[t] = o4;
}

// ---------------- launch ----------------
extern "C" void kernel_launch(void* const* d_in, const int* in_sizes, int n_in,
                              void* d_out, int out_size)
{
    const float* x     = (const float*)d_in[0];
    const float* wq    = (const float*)d_in[1];
    const float* bq    = (const float*)d_in[2];
    const float* wk    = (const float*)d_in[3];
    const float* bk    = (const float*)d_in[4];
    const float* wv    = (const float*)d_in[5];
    const float* bv    = (const float*)d_in[6];
    const float* wo    = (const float*)d_in[7];
    const float* bo    = (const float*)d_in[8];
    const float* gamma = (const float*)d_in[9];
    const float* beta  = (const float*)d_in[10];

    float *q, *k, *v, *ctx, *hbuf;
    cudaGetSymbolAddress((void**)&q,    g_q);
    cudaGetSymbolAddress((void**)&k,    g_k);
    cudaGetSymbolAddress((void**)&v,    g_v);
    cudaGetSymbolAddress((void**)&ctx,  g_ctx);
    cudaGetSymbolAddress((void**)&hbuf, g_h);

    dim3 gb(H_ / BN, MTOT / BM);   // (8, 64)
    dim3 tb(256);

    gemm_bf16x3<<<gb, tb>>>(x, wq, bq, nullptr, q, 1);
    gemm_bf16x3<<<gb, tb>>>(x, wk, bk, nullptr, k, 1);
    gemm_bf16x3<<<gb, tb>>>(x, wv, bv, nullptr, v, 1);

    flash_attn2<<<dim3(S_ / BQ, NH_, B_), 256>>>(q, k, v, ctx);

    gemm_bf16x3<<<gb, tb>>>(ctx, wo, bo, x, hbuf, 0);

    layernorm_k<<<MTOT, 256>>>(hbuf, gamma, beta, (float*)d_out);
}

// round 4
// speedup vs baseline: 1.7132x; 1.3825x over previous
#include <cuda_runtime.h>
#include <cuda_bf16.h>
#include <math.h>
#include <stdint.h>

#define B_   4
#define S_   2048
#define H_   1024
#define NH_  16
#define HD_  64
#define MTOT (B_ * S_)   // 8192

// ---------------- scratch (no allocs allowed) ----------------
__device__ float g_q[(size_t)B_ * NH_ * S_ * HD_];    // [B,NH,S,HD]
__device__ float g_k[(size_t)B_ * NH_ * S_ * HD_];
__device__ float g_v[(size_t)B_ * NH_ * S_ * HD_];
__device__ float g_ctx[(size_t)B_ * S_ * H_];         // [B,S,H]
__device__ float g_h[(size_t)B_ * S_ * H_];           // pre-LN

// ---------------- common PTX helpers ----------------
__device__ __forceinline__ void mma16816(float* c, const uint32_t* a, const uint32_t* b) {
    asm volatile(
        "mma.sync.aligned.m16n8k16.row.col.f32.bf16.bf16.f32 "
        "{%0,%1,%2,%3}, {%4,%5,%6,%7}, {%8,%9}, {%0,%1,%2,%3};\n"
        : "+f"(c[0]), "+f"(c[1]), "+f"(c[2]), "+f"(c[3])
        : "r"(a[0]), "r"(a[1]), "r"(a[2]), "r"(a[3]), "r"(b[0]), "r"(b[1]));
}
__device__ __forceinline__ void ldsm_x4(uint32_t* r, uint32_t addr) {
    asm volatile(
        "ldmatrix.sync.aligned.m8n8.x4.shared.b16 {%0,%1,%2,%3}, [%4];\n"
        : "=r"(r[0]), "=r"(r[1]), "=r"(r[2]), "=r"(r[3]) : "r"(addr));
}
__device__ __forceinline__ void ldsm_x4_t(uint32_t* r, uint32_t addr) {
    asm volatile(
        "ldmatrix.sync.aligned.m8n8.x4.trans.shared.b16 {%0,%1,%2,%3}, [%4];\n"
        : "=r"(r[0]), "=r"(r[1]), "=r"(r[2]), "=r"(r[3]) : "r"(addr));
}
__device__ __forceinline__ void split2(float x, float y, uint32_t& hi, uint32_t& lo) {
    __nv_bfloat16 hx = __float2bfloat16(x), hy = __float2bfloat16(y);
    __nv_bfloat16 lx = __float2bfloat16(x - __bfloat162float(hx));
    __nv_bfloat16 ly = __float2bfloat16(y - __bfloat162float(hy));
    __nv_bfloat162 h2 = __halves2bfloat162(hx, hy);
    __nv_bfloat162 l2 = __halves2bfloat162(lx, ly);
    hi = *(uint32_t*)&h2;
    lo = *(uint32_t*)&l2;
}

// ============================================================
//  bf16x3 tensor-core GEMM:  C[M,N] = A[M,K] * W[N,K]^T + bias
// ============================================================
#define BM 128
#define BN 128
#define BK 32
#define LDS_PAD 8
#define LDK (BK + LDS_PAD)

__global__ __launch_bounds__(256) void gemm_bf16x3(
    const float* __restrict__ A, const float* __restrict__ W,
    const float* __restrict__ bias, const float* __restrict__ resid,
    float* __restrict__ C, int qkv_layout)
{
    const int K = H_, N = H_;
    __shared__ __nv_bfloat16 Ah[BM][LDK], Al[BM][LDK];
    __shared__ __nv_bfloat16 Bh[BN][LDK], Bl[BN][LDK];

    const int tid  = threadIdx.x;
    const int warp = tid >> 5;
    const int lane = tid & 31;
    const int rowBase = blockIdx.y * BM;
    const int colBase = blockIdx.x * BN;

    const int m0 = (warp >> 1) * 32;
    const int n0 = (warp & 1) * 64;

    const int lrow = tid >> 1;
    const int lcol = (tid & 1) * 16;
    const float* Ag = A + (size_t)(rowBase + lrow) * K + lcol;
    const float* Wg = W + (size_t)(colBase + lrow) * K + lcol;

    const int a_row = m0 + ((lane >> 3) & 1) * 8 + (lane & 7);
    const int a_col = ((lane >> 4) & 1) * 8;
    const int b_row = n0 + ((lane >> 4) & 1) * 8 + (lane & 7);
    const int b_col = ((lane >> 3) & 1) * 8;

    const uint32_t sAh = (uint32_t)__cvta_generic_to_shared(&Ah[0][0]);
    const uint32_t sAl = (uint32_t)__cvta_generic_to_shared(&Al[0][0]);
    const uint32_t sBh = (uint32_t)__cvta_generic_to_shared(&Bh[0][0]);
    const uint32_t sBl = (uint32_t)__cvta_generic_to_shared(&Bl[0][0]);

    float acc[2][8][4];
#pragma unroll
    for (int i = 0; i < 2; i++)
#pragma unroll
        for (int j = 0; j < 8; j++)
#pragma unroll
            for (int r = 0; r < 4; r++) acc[i][j][r] = 0.f;

    float4 ra[4], rb[4];
#pragma unroll
    for (int v = 0; v < 4; v++) {
        ra[v] = *(const float4*)(Ag + v * 4);
        rb[v] = *(const float4*)(Wg + v * 4);
    }

    for (int kt = 0; kt < K; kt += BK) {
#pragma unroll
        for (int v = 0; v < 4; v++) {
            const float* fa = (const float*)&ra[v];
            const float* fb = (const float*)&rb[v];
#pragma unroll
            for (int e = 0; e < 4; e++) {
                int c = lcol + v * 4 + e;
                __nv_bfloat16 h = __float2bfloat16(fa[e]);
                Ah[lrow][c] = h;
                Al[lrow][c] = __float2bfloat16(fa[e] - __bfloat162float(h));
                __nv_bfloat16 g = __float2bfloat16(fb[e]);
                Bh[lrow][c] = g;
                Bl[lrow][c] = __float2bfloat16(fb[e] - __bfloat162float(g));
            }
        }
        __syncthreads();

        if (kt + BK < K) {
#pragma unroll
            for (int v = 0; v < 4; v++) {
                ra[v] = *(const float4*)(Ag + kt + BK + v * 4);
                rb[v] = *(const float4*)(Wg + kt + BK + v * 4);
            }
        }

#pragma unroll
        for (int ks = 0; ks < 2; ks++) {
            const int kb = ks * 16;
            uint32_t ah[2][4], al[2][4], bh[8][2], bl[8][2];
#pragma unroll
            for (int mi = 0; mi < 2; mi++) {
                uint32_t off = (uint32_t)(((a_row + mi * 16) * LDK) + kb + a_col) * 2;
                ldsm_x4(ah[mi], sAh + off);
                ldsm_x4(al[mi], sAl + off);
            }
#pragma unroll
            for (int p = 0; p < 4; p++) {
                uint32_t off = (uint32_t)(((b_row + p * 16) * LDK) + kb + b_col) * 2;
                uint32_t t[4];
                ldsm_x4(t, sBh + off);
                bh[2 * p][0] = t[0]; bh[2 * p][1] = t[1];
                bh[2 * p + 1][0] = t[2]; bh[2 * p + 1][1] = t[3];
                ldsm_x4(t, sBl + off);
                bl[2 * p][0] = t[0]; bl[2 * p][1] = t[1];
                bl[2 * p + 1][0] = t[2]; bl[2 * p + 1][1] = t[3];
            }
#pragma unroll
            for (int nj = 0; nj < 8; nj++)
#pragma unroll
                for (int mi = 0; mi < 2; mi++) {
                    mma16816(acc[mi][nj], ah[mi], bh[nj]);
                    mma16816(acc[mi][nj], ah[mi], bl[nj]);
                    mma16816(acc[mi][nj], al[mi], bh[nj]);
                }
        }
        __syncthreads();
    }

    const int g  = lane >> 2;
    const int t2 = (lane & 3) * 2;
#pragma unroll
    for (int mi = 0; mi < 2; mi++) {
#pragma unroll
        for (int nj = 0; nj < 8; nj++) {
            int n = colBase + n0 + nj * 8 + t2;
            float bia0 = bias[n], bia1 = bias[n + 1];
#pragma unroll
            for (int rr = 0; rr < 2; rr++) {
                int m = rowBase + m0 + mi * 16 + g + rr * 8;
                float v0 = acc[mi][nj][rr * 2 + 0] + bia0;
                float v1 = acc[mi][nj][rr * 2 + 1] + bia1;
                if (qkv_layout) {
                    int bb = m >> 11, ss = m & (S_ - 1);
                    int hh = n >> 6, dd = n & (HD_ - 1);
                    float2* dst = (float2*)&C[((((size_t)bb * NH_) + hh) * S_ + ss) * HD_ + dd];
                    *dst = make_float2(v0, v1);
                } else {
                    const float2 rs = *(const float2*)&resid[(size_t)m * N + n];
                    *(float2*)&C[(size_t)m * N + n] = make_float2(v0 + rs.x, v1 + rs.y);
                }
            }
        }
    }
}

// ============================================================
//  MMA flash attention (bf16x3 emulated), 64 q x 64 kv tiles
//  128 threads: warp w owns q rows [16w, 16w+16)
// ============================================================
#define FLDV 72   // padded row stride (halves): conflict-free ldmatrix

__global__ __launch_bounds__(128) void flash_mma(
    const float* __restrict__ Q, const float* __restrict__ Kg,
    const float* __restrict__ Vg, float* __restrict__ ctx)
{
    __shared__ __nv_bfloat16 Kh[64][FLDV], Kl[64][FLDV];
    __shared__ __nv_bfloat16 Vh[64][FLDV], Vl[64][FLDV];

    const int b = blockIdx.z;
    const int h = blockIdx.y;
    const int tid  = threadIdx.x;
    const int warp = tid >> 5;
    const int lane = tid & 31;
    const int q0 = blockIdx.x * 64;

    const size_t headBase = (((size_t)b * NH_ + h) * S_) * HD_;
    const float* qbase = Q  + headBase;
    const float* kbase = Kg + headBase;
    const float* vbase = Vg + headBase;

    // cooperative load mapping: thread t -> row t>>1, cols (t&1)*32..+31
    const int lrow = tid >> 1;
    const int lcol = (tid & 1) * 32;

    // ldmatrix lane patterns
    const int a_row = ((lane >> 3) & 1) * 8 + (lane & 7);   // A operand (Q / rows)
    const int a_col = ((lane >> 4) & 1) * 8;
    const int b_row = ((lane >> 4) & 1) * 8 + (lane & 7);   // B operand (K keys)
    const int b_col = ((lane >> 3) & 1) * 8;
    const int v_row = ((lane >> 3) & 1) * 8 + (lane & 7);   // V (trans) keys
    const int v_col = ((lane >> 4) & 1) * 8;                // V d offset

    const uint32_t sKh = (uint32_t)__cvta_generic_to_shared(&Kh[0][0]);
    const uint32_t sKl = (uint32_t)__cvta_generic_to_shared(&Kl[0][0]);
    const uint32_t sVh = (uint32_t)__cvta_generic_to_shared(&Vh[0][0]);
    const uint32_t sVl = (uint32_t)__cvta_generic_to_shared(&Vl[0][0]);

    // ---- stage Q (scaled by 1/8) through K smem, pull fragments ----
    {
        const float* qg = qbase + (size_t)(q0 + lrow) * HD_ + lcol;
#pragma unroll
        for (int v = 0; v < 8; v++) {
            float4 f = *(const float4*)(qg + v * 4);
            const float* fe = (const float*)&f;
#pragma unroll
            for (int e = 0; e < 4; e++) {
                float x = fe[e] * 0.125f;             // fold softmax scale
                int c = lcol + v * 4 + e;
                __nv_bfloat16 hi = __float2bfloat16(x);
                Kh[lrow][c] = hi;
                Kl[lrow][c] = __float2bfloat16(x - __bfloat162float(hi));
            }
        }
    }
    __syncthreads();

    uint32_t qh[4][4], ql[4][4];
#pragma unroll
    for (int ks = 0; ks < 4; ks++) {
        uint32_t off = (uint32_t)(((warp * 16 + a_row) * FLDV) + ks * 16 + a_col) * 2;
        ldsm_x4(qh[ks], sKh + off);
        ldsm_x4(ql[ks], sKl + off);
    }
    __syncthreads();

    // ---- running state ----
    float o[8][4];
#pragma unroll
    for (int dn = 0; dn < 8; dn++)
#pragma unroll
        for (int e = 0; e < 4; e++) o[dn][e] = 0.f;
    float mrun[2] = {-1e30f, -1e30f};
    float lrun[2] = {0.f, 0.f};

    for (int j0 = 0; j0 < S_; j0 += 64) {
        // ---- load + convert K,V tiles ----
        {
            const float* kg = kbase + (size_t)(j0 + lrow) * HD_ + lcol;
            const float* vg = vbase + (size_t)(j0 + lrow) * HD_ + lcol;
#pragma unroll
            for (int v = 0; v < 8; v++) {
                float4 fk = *(const float4*)(kg + v * 4);
                float4 fv = *(const float4*)(vg + v * 4);
                const float* ke = (const float*)&fk;
                const float* ve = (const float*)&fv;
#pragma unroll
                for (int e = 0; e < 4; e++) {
                    int c = lcol + v * 4 + e;
                    __nv_bfloat16 hk = __float2bfloat16(ke[e]);
                    Kh[lrow][c] = hk;
                    Kl[lrow][c] = __float2bfloat16(ke[e] - __bfloat162float(hk));
                    __nv_bfloat16 hv = __float2bfloat16(ve[e]);
                    Vh[lrow][c] = hv;
                    Vl[lrow][c] = __float2bfloat16(ve[e] - __bfloat162float(hv));
                }
            }
        }
        __syncthreads();

        // ---- S = Q K^T (scaled), fp32-emulated ----
        float sacc[8][4];
#pragma unroll
        for (int nj = 0; nj < 8; nj++)
#pragma unroll
            for (int e = 0; e < 4; e++) sacc[nj][e] = 0.f;

#pragma unroll
        for (int ks = 0; ks < 4; ks++) {
            uint32_t bh[8][2], bl[8][2];
#pragma unroll
            for (int p = 0; p < 4; p++) {
                uint32_t off = (uint32_t)(((p * 16 + b_row) * FLDV) + ks * 16 + b_col) * 2;
                uint32_t t[4];
                ldsm_x4(t, sKh + off);
                bh[2 * p][0] = t[0]; bh[2 * p][1] = t[1];
                bh[2 * p + 1][0] = t[2]; bh[2 * p + 1][1] = t[3];
                ldsm_x4(t, sKl + off);
                bl[2 * p][0] = t[0]; bl[2 * p][1] = t[1];
                bl[2 * p + 1][0] = t[2]; bl[2 * p + 1][1] = t[3];
            }
#pragma unroll
            for (int nj = 0; nj < 8; nj++) {
                mma16816(sacc[nj], qh[ks], bh[nj]);
                mma16816(sacc[nj], ql[ks], bh[nj]);
                mma16816(sacc[nj], qh[ks], bl[nj]);
            }
        }

        // ---- online softmax (rows g and g+8 per thread) ----
        float mloc[2] = {-1e30f, -1e30f};
#pragma unroll
        for (int nj = 0; nj < 8; nj++) {
            mloc[0] = fmaxf(mloc[0], fmaxf(sacc[nj][0], sacc[nj][1]));
            mloc[1] = fmaxf(mloc[1], fmaxf(sacc[nj][2], sacc[nj][3]));
        }
#pragma unroll
        for (int r = 0; r < 2; r++) {
            mloc[r] = fmaxf(mloc[r], __shfl_xor_sync(0xFFFFFFFFu, mloc[r], 1));
            mloc[r] = fmaxf(mloc[r], __shfl_xor_sync(0xFFFFFFFFu, mloc[r], 2));
        }
        float corr[2];
#pragma unroll
        for (int r = 0; r < 2; r++) {
            float mnew = fmaxf(mrun[r], mloc[r]);
            corr[r] = __expf(mrun[r] - mnew);
            mrun[r] = mnew;
        }
        float psum[2] = {0.f, 0.f};
#pragma unroll
        for (int nj = 0; nj < 8; nj++) {
            float p0 = __expf(sacc[nj][0] - mrun[0]);
            float p1 = __expf(sacc[nj][1] - mrun[0]);
            float p2 = __expf(sacc[nj][2] - mrun[1]);
            float p3 = __expf(sacc[nj][3] - mrun[1]);
            sacc[nj][0] = p0; sacc[nj][1] = p1;
            sacc[nj][2] = p2; sacc[nj][3] = p3;
            psum[0] += p0 + p1;
            psum[1] += p2 + p3;
        }
#pragma unroll
        for (int r = 0; r < 2; r++) {
            psum[r] += __shfl_xor_sync(0xFFFFFFFFu, psum[r], 1);
            psum[r] += __shfl_xor_sync(0xFFFFFFFFu, psum[r], 2);
            lrun[r] = lrun[r] * corr[r] + psum[r];
        }
#pragma unroll
        for (int dn = 0; dn < 8; dn++) {
            o[dn][0] *= corr[0]; o[dn][1] *= corr[0];
            o[dn][2] *= corr[1]; o[dn][3] *= corr[1];
        }

        // ---- repack P (C-frag) -> A-frags, hi/lo split ----
        uint32_t ph[4][4], pl[4][4];
#pragma unroll
        for (int ks = 0; ks < 4; ks++) {
            const float* c0 = sacc[2 * ks];
            const float* c1 = sacc[2 * ks + 1];
            split2(c0[0], c0[1], ph[ks][0], pl[ks][0]);
            split2(c0[2], c0[3], ph[ks][1], pl[ks][1]);
            split2(c1[0], c1[1], ph[ks][2], pl[ks][2]);
            split2(c1[2], c1[3], ph[ks][3], pl[ks][3]);
        }

        // ---- O += P V ----
#pragma unroll
        for (int ks = 0; ks < 4; ks++) {
            uint32_t vbh[8][2], vbl[8][2];
#pragma unroll
            for (int p = 0; p < 4; p++) {
                uint32_t off = (uint32_t)(((ks * 16 + v_row) * FLDV) + p * 16 + v_col) * 2;
                uint32_t t[4];
                ldsm_x4_t(t, sVh + off);
                vbh[2 * p][0] = t[0]; vbh[2 * p][1] = t[1];
                vbh[2 * p + 1][0] = t[2]; vbh[2 * p + 1][1] = t[3];
                ldsm_x4_t(t, sVl + off);
                vbl[2 * p][0] = t[0]; vbl[2 * p][1] = t[1];
                vbl[2 * p + 1][0] = t[2]; vbl[2 * p + 1][1] = t[3];
            }
#pragma unroll
            for (int dn = 0; dn < 8; dn++) {
                mma16816(o[dn], ph[ks], vbh[dn]);
                mma16816(o[dn], pl[ks], vbh[dn]);
                mma16816(o[dn], ph[ks], vbl[dn]);
            }
        }
        __syncthreads();
    }

    // ---- finalize + write ctx [B,S,H] ----
    const int g  = lane >> 2;
    const int t2 = (lane & 3) * 2;
    float inv0 = 1.0f / lrun[0];
    float inv1 = 1.0f / lrun[1];
#pragma unroll
    for (int dn = 0; dn < 8; dn++) {
        int d = h * HD_ + dn * 8 + t2;
        int m0g = q0 + warp * 16 + g;
        float* dst0 = &ctx[((size_t)b * S_ + m0g) * H_ + d];
        float* dst1 = &ctx[((size_t)b * S_ + m0g + 8) * H_ + d];
        *(float2*)dst0 = make_float2(o[dn][0] * inv0, o[dn][1] * inv0);
        *(float2*)dst1 = make_float2(o[dn][2] * inv1, o[dn][3] * inv1);
    }
}

// ---------------- layernorm (one block per row) --------------------------
__global__ __launch_bounds__(256) void layernorm_k(
    const float* __restrict__ hin, const float* __restrict__ gamma,
    const float* __restrict__ beta, float* __restrict__ out)
{
    const int row = blockIdx.x;
    const int t = threadIdx.x;
    const float* hp = hin + (size_t)row * H_;
    float* op = out + (size_t)row * H_;

    float4 x4 = ((const float4*)hp)[t];
    float sum = x4.x + x4.y + x4.z + x4.w;
    float sq  = x4.x * x4.x + x4.y * x4.y + x4.z * x4.z + x4.w * x4.w;

#pragma unroll
    for (int off = 16; off > 0; off >>= 1) {
        sum += __shfl_xor_sync(0xFFFFFFFFu, sum, off);
        sq  += __shfl_xor_sync(0xFFFFFFFFu, sq,  off);
    }
    __shared__ float ssum[8], ssq[8];
    const int wid = t >> 5, lid = t & 31;
    if (lid == 0) { ssum[wid] = sum; ssq[wid] = sq; }
    __syncthreads();
    if (wid == 0) {
        float a = (lid < 8) ? ssum[lid] : 0.f;
        float b = (lid < 8) ? ssq[lid]  : 0.f;
#pragma unroll
        for (int off = 4; off > 0; off >>= 1) {
            a += __shfl_xor_sync(0xFFFFFFFFu, a, off);
            b += __shfl_xor_sync(0xFFFFFFFFu, b, off);
        }
        if (lid == 0) { ssum[0] = a; ssq[0] = b; }
    }
    __syncthreads();
    const float mean = ssum[0] * (1.0f / H_);
    const float var  = ssq[0] * (1.0f / H_) - mean * mean;
    const float rstd = rsqrtf(var + 1e-12f);

    float4 g4 = ((const float4*)gamma)[t];
    float4 b4 = ((const float4*)beta)[t];
    float4 o4;
    o4.x = g4.x * (x4.x - mean) * rstd + b4.x;
    o4.y = g4.y * (x4.y - mean) * rstd + b4.y;
    o4.z = g4.z * (x4.z - mean) * rstd + b4.z;
    o4.w = g4.w * (x4.w - mean) * rstd + b4.w;
    ((float4*)op)[t] = o4;
}

// ---------------- launch ----------------
extern "C" void kernel_launch(void* const* d_in, const int* in_sizes, int n_in,
                              void* d_out, int out_size)
{
    const float* x     = (const float*)d_in[0];
    const float* wq    = (const float*)d_in[1];
    const float* bq    = (const float*)d_in[2];
    const float* wk    = (const float*)d_in[3];
    const float* bk    = (const float*)d_in[4];
    const float* wv    = (const float*)d_in[5];
    const float* bv    = (const float*)d_in[6];
    const float* wo    = (const float*)d_in[7];
    const float* bo    = (const float*)d_in[8];
    const float* gamma = (const float*)d_in[9];
    const float* beta  = (const float*)d_in[10];

    float *q, *k, *v, *ctx, *hbuf;
    cudaGetSymbolAddress((void**)&q,    g_q);
    cudaGetSymbolAddress((void**)&k,    g_k);
    cudaGetSymbolAddress((void**)&v,    g_v);
    cudaGetSymbolAddress((void**)&ctx,  g_ctx);
    cudaGetSymbolAddress((void**)&hbuf, g_h);

    dim3 gb(H_ / BN, MTOT / BM);   // (8, 64)
    dim3 tb(256);

    gemm_bf16x3<<<gb, tb>>>(x, wq, bq, nullptr, q, 1);
    gemm_bf16x3<<<gb, tb>>>(x, wk, bk, nullptr, k, 1);
    gemm_bf16x3<<<gb, tb>>>(x, wv, bv, nullptr, v, 1);

    flash_mma<<<dim3(S_ / 64, NH_, B_), 128>>>(q, k, v, ctx);

    gemm_bf16x3<<<gb, tb>>>(ctx, wo, bo, x, hbuf, 0);

    layernorm_k<<<MTOT, 256>>>(hbuf, gamma, beta, (float*)d_out);
}

// round 5
// speedup vs baseline: 2.7233x; 1.5896x over previous
#include <cuda_runtime.h>
#include <cuda_bf16.h>
#include <math.h>
#include <stdint.h>

#define B_   4
#define S_   2048
#define H_   1024
#define NH_  16
#define HD_  64
#define MTOT (B_ * S_)   // 8192

// ---------------- scratch (no allocs allowed) ----------------
__device__ float g_q[(size_t)B_ * NH_ * S_ * HD_];    // [B,NH,S,HD]
__device__ float g_k[(size_t)B_ * NH_ * S_ * HD_];
__device__ float g_v[(size_t)B_ * NH_ * S_ * HD_];
__device__ float g_ctx[(size_t)B_ * S_ * H_];         // [B,S,H]
__device__ float g_h[(size_t)B_ * S_ * H_];           // pre-LN

// ---------------- common PTX helpers ----------------
__device__ __forceinline__ void mma16816(float* c, const uint32_t* a, const uint32_t* b) {
    asm volatile(
        "mma.sync.aligned.m16n8k16.row.col.f32.bf16.bf16.f32 "
        "{%0,%1,%2,%3}, {%4,%5,%6,%7}, {%8,%9}, {%0,%1,%2,%3};\n"
        : "+f"(c[0]), "+f"(c[1]), "+f"(c[2]), "+f"(c[3])
        : "r"(a[0]), "r"(a[1]), "r"(a[2]), "r"(a[3]), "r"(b[0]), "r"(b[1]));
}
__device__ __forceinline__ void ldsm_x4(uint32_t* r, uint32_t addr) {
    asm volatile(
        "ldmatrix.sync.aligned.m8n8.x4.shared.b16 {%0,%1,%2,%3}, [%4];\n"
        : "=r"(r[0]), "=r"(r[1]), "=r"(r[2]), "=r"(r[3]) : "r"(addr));
}
__device__ __forceinline__ void ldsm_x4_t(uint32_t* r, uint32_t addr) {
    asm volatile(
        "ldmatrix.sync.aligned.m8n8.x4.trans.shared.b16 {%0,%1,%2,%3}, [%4];\n"
        : "=r"(r[0]), "=r"(r[1]), "=r"(r[2]), "=r"(r[3]) : "r"(addr));
}
// split two floats -> packed bf16x2 hi and lo
__device__ __forceinline__ void split2(float x, float y, uint32_t& hi, uint32_t& lo) {
    __nv_bfloat16 hx = __float2bfloat16(x), hy = __float2bfloat16(y);
    __nv_bfloat16 lx = __float2bfloat16(x - __bfloat162float(hx));
    __nv_bfloat16 ly = __float2bfloat16(y - __bfloat162float(hy));
    __nv_bfloat162 h2 = __halves2bfloat162(hx, hy);
    __nv_bfloat162 l2 = __halves2bfloat162(lx, ly);
    hi = *(uint32_t*)&h2;
    lo = *(uint32_t*)&l2;
}

// ============================================================
//  bf16x3 tensor-core GEMM:  C[M,N] = A[M,K] * W[N,K]^T + bias
//  gridDim.z selects weight set (QKV fused); vectorized STS.
// ============================================================
#define BM 128
#define BN 128
#define BK 32
#define LDS_PAD 8
#define LDK (BK + LDS_PAD)     // 40 halves = 80 B row stride (16B-aligned)

__global__ __launch_bounds__(256) void gemm_bf16x3(
    const float* __restrict__ A,
    const float* __restrict__ W0, const float* __restrict__ W1, const float* __restrict__ W2,
    const float* __restrict__ bias0, const float* __restrict__ bias1, const float* __restrict__ bias2,
    float* __restrict__ C0, float* __restrict__ C1, float* __restrict__ C2,
    const float* __restrict__ resid, int qkv_layout)
{
    const int K = H_, N = H_;
    const int z = blockIdx.z;
    const float* W    = (z == 0) ? W0 : (z == 1) ? W1 : W2;
    const float* bias = (z == 0) ? bias0 : (z == 1) ? bias1 : bias2;
    float*       C    = (z == 0) ? C0 : (z == 1) ? C1 : C2;

    __shared__ __nv_bfloat16 Ah[BM][LDK], Al[BM][LDK];
    __shared__ __nv_bfloat16 Bh[BN][LDK], Bl[BN][LDK];

    const int tid  = threadIdx.x;
    const int warp = tid >> 5;
    const int lane = tid & 31;
    const int rowBase = blockIdx.y * BM;
    const int colBase = blockIdx.x * BN;

    const int m0 = (warp >> 1) * 32;
    const int n0 = (warp & 1) * 64;

    const int lrow = tid >> 1;
    const int lcol = (tid & 1) * 16;
    const float* Ag = A + (size_t)(rowBase + lrow) * K + lcol;
    const float* Wg = W + (size_t)(colBase + lrow) * K + lcol;

    const int a_row = m0 + ((lane >> 3) & 1) * 8 + (lane & 7);
    const int a_col = ((lane >> 4) & 1) * 8;
    const int b_row = n0 + ((lane >> 4) & 1) * 8 + (lane & 7);
    const int b_col = ((lane >> 3) & 1) * 8;

    const uint32_t sAh = (uint32_t)__cvta_generic_to_shared(&Ah[0][0]);
    const uint32_t sAl = (uint32_t)__cvta_generic_to_shared(&Al[0][0]);
    const uint32_t sBh = (uint32_t)__cvta_generic_to_shared(&Bh[0][0]);
    const uint32_t sBl = (uint32_t)__cvta_generic_to_shared(&Bl[0][0]);

    float acc[2][8][4];
#pragma unroll
    for (int i = 0; i < 2; i++)
#pragma unroll
        for (int j = 0; j < 8; j++)
#pragma unroll
            for (int r = 0; r < 4; r++) acc[i][j][r] = 0.f;

    float4 ra[4], rb[4];
#pragma unroll
    for (int v = 0; v < 4; v++) {
        ra[v] = *(const float4*)(Ag + v * 4);
        rb[v] = *(const float4*)(Wg + v * 4);
    }

    for (int kt = 0; kt < K; kt += BK) {
        // convert + packed store (STS.128)
        {
            uint32_t ahp[8], alp[8], bhp[8], blp[8];
#pragma unroll
            for (int v = 0; v < 4; v++) {
                const float* fa = (const float*)&ra[v];
                const float* fb = (const float*)&rb[v];
                split2(fa[0], fa[1], ahp[2 * v], alp[2 * v]);
                split2(fa[2], fa[3], ahp[2 * v + 1], alp[2 * v + 1]);
                split2(fb[0], fb[1], bhp[2 * v], blp[2 * v]);
                split2(fb[2], fb[3], bhp[2 * v + 1], blp[2 * v + 1]);
            }
            float4* dAh = (float4*)&Ah[lrow][lcol];
            float4* dAl = (float4*)&Al[lrow][lcol];
            float4* dBh = (float4*)&Bh[lrow][lcol];
            float4* dBl = (float4*)&Bl[lrow][lcol];
            dAh[0] = ((float4*)ahp)[0]; dAh[1] = ((float4*)ahp)[1];
            dAl[0] = ((float4*)alp)[0]; dAl[1] = ((float4*)alp)[1];
            dBh[0] = ((float4*)bhp)[0]; dBh[1] = ((float4*)bhp)[1];
            dBl[0] = ((float4*)blp)[0]; dBl[1] = ((float4*)blp)[1];
        }
        __syncthreads();

        if (kt + BK < K) {
#pragma unroll
            for (int v = 0; v < 4; v++) {
                ra[v] = *(const float4*)(Ag + kt + BK + v * 4);
                rb[v] = *(const float4*)(Wg + kt + BK + v * 4);
            }
        }

#pragma unroll
        for (int ks = 0; ks < 2; ks++) {
            const int kb = ks * 16;
            uint32_t ah[2][4], al[2][4], bh[8][2], bl[8][2];
#pragma unroll
            for (int mi = 0; mi < 2; mi++) {
                uint32_t off = (uint32_t)(((a_row + mi * 16) * LDK) + kb + a_col) * 2;
                ldsm_x4(ah[mi], sAh + off);
                ldsm_x4(al[mi], sAl + off);
            }
#pragma unroll
            for (int p = 0; p < 4; p++) {
                uint32_t off = (uint32_t)(((b_row + p * 16) * LDK) + kb + b_col) * 2;
                uint32_t t[4];
                ldsm_x4(t, sBh + off);
                bh[2 * p][0] = t[0]; bh[2 * p][1] = t[1];
                bh[2 * p + 1][0] = t[2]; bh[2 * p + 1][1] = t[3];
                ldsm_x4(t, sBl + off);
                bl[2 * p][0] = t[0]; bl[2 * p][1] = t[1];
                bl[2 * p + 1][0] = t[2]; bl[2 * p + 1][1] = t[3];
            }
#pragma unroll
            for (int nj = 0; nj < 8; nj++)
#pragma unroll
                for (int mi = 0; mi < 2; mi++) {
                    mma16816(acc[mi][nj], ah[mi], bh[nj]);
                    mma16816(acc[mi][nj], ah[mi], bl[nj]);
                    mma16816(acc[mi][nj], al[mi], bh[nj]);
                }
        }
        __syncthreads();
    }

    const int g  = lane >> 2;
    const int t2 = (lane & 3) * 2;
#pragma unroll
    for (int mi = 0; mi < 2; mi++) {
#pragma unroll
        for (int nj = 0; nj < 8; nj++) {
            int n = colBase + n0 + nj * 8 + t2;
            float bia0 = bias[n], bia1 = bias[n + 1];
#pragma unroll
            for (int rr = 0; rr < 2; rr++) {
                int m = rowBase + m0 + mi * 16 + g + rr * 8;
                float v0 = acc[mi][nj][rr * 2 + 0] + bia0;
                float v1 = acc[mi][nj][rr * 2 + 1] + bia1;
                if (qkv_layout) {
                    int bb = m >> 11, ss = m & (S_ - 1);
                    int hh = n >> 6, dd = n & (HD_ - 1);
                    float2* dst = (float2*)&C[((((size_t)bb * NH_) + hh) * S_ + ss) * HD_ + dd];
                    *dst = make_float2(v0, v1);
                } else {
                    const float2 rs = *(const float2*)&resid[(size_t)m * N + n];
                    *(float2*)&C[(size_t)m * N + n] = make_float2(v0 + rs.x, v1 + rs.y);
                }
            }
        }
    }
}

// ============================================================
//  MMA flash attention (bf16x3 emulated), 64 q x 64 kv tiles
//  128 threads: warp w owns q rows [16w, 16w+16)
// ============================================================
#define FLDV 72   // padded row stride (halves) = 144 B (16B-aligned)

__global__ __launch_bounds__(128) void flash_mma(
    const float* __restrict__ Q, const float* __restrict__ Kg,
    const float* __restrict__ Vg, float* __restrict__ ctx)
{
    __shared__ __nv_bfloat16 Kh[64][FLDV], Kl[64][FLDV];
    __shared__ __nv_bfloat16 Vh[64][FLDV], Vl[64][FLDV];

    const int b = blockIdx.z;
    const int h = blockIdx.y;
    const int tid  = threadIdx.x;
    const int warp = tid >> 5;
    const int lane = tid & 31;
    const int q0 = blockIdx.x * 64;

    const size_t headBase = (((size_t)b * NH_ + h) * S_) * HD_;
    const float* qbase = Q  + headBase;
    const float* kbase = Kg + headBase;
    const float* vbase = Vg + headBase;

    const int lrow = tid >> 1;
    const int lcol = (tid & 1) * 32;

    const int a_row = ((lane >> 3) & 1) * 8 + (lane & 7);
    const int a_col = ((lane >> 4) & 1) * 8;
    const int b_row = ((lane >> 4) & 1) * 8 + (lane & 7);
    const int b_col = ((lane >> 3) & 1) * 8;
    const int v_row = ((lane >> 3) & 1) * 8 + (lane & 7);
    const int v_col = ((lane >> 4) & 1) * 8;

    const uint32_t sKh = (uint32_t)__cvta_generic_to_shared(&Kh[0][0]);
    const uint32_t sKl = (uint32_t)__cvta_generic_to_shared(&Kl[0][0]);
    const uint32_t sVh = (uint32_t)__cvta_generic_to_shared(&Vh[0][0]);
    const uint32_t sVl = (uint32_t)__cvta_generic_to_shared(&Vl[0][0]);

    // ---- stage Q (scaled by 1/8) through K smem, packed stores ----
    {
        const float* qg = qbase + (size_t)(q0 + lrow) * HD_ + lcol;
        uint32_t qhp[16], qlp[16];
#pragma unroll
        for (int v = 0; v < 8; v++) {
            float4 f = *(const float4*)(qg + v * 4);
            split2(f.x * 0.125f, f.y * 0.125f, qhp[2 * v], qlp[2 * v]);
            split2(f.z * 0.125f, f.w * 0.125f, qhp[2 * v + 1], qlp[2 * v + 1]);
        }
        float4* dH = (float4*)&Kh[lrow][lcol];
        float4* dL = (float4*)&Kl[lrow][lcol];
#pragma unroll
        for (int i = 0; i < 4; i++) {
            dH[i] = ((float4*)qhp)[i];
            dL[i] = ((float4*)qlp)[i];
        }
    }
    __syncthreads();

    uint32_t qh[4][4], ql[4][4];
#pragma unroll
    for (int ks = 0; ks < 4; ks++) {
        uint32_t off = (uint32_t)(((warp * 16 + a_row) * FLDV) + ks * 16 + a_col) * 2;
        ldsm_x4(qh[ks], sKh + off);
        ldsm_x4(ql[ks], sKl + off);
    }
    __syncthreads();

    float o[8][4];
#pragma unroll
    for (int dn = 0; dn < 8; dn++)
#pragma unroll
        for (int e = 0; e < 4; e++) o[dn][e] = 0.f;
    float mrun[2] = {-1e30f, -1e30f};
    float lrun[2] = {0.f, 0.f};

    for (int j0 = 0; j0 < S_; j0 += 64) {
        // ---- load + convert K,V tiles (packed STS.128) ----
        {
            const float* kg = kbase + (size_t)(j0 + lrow) * HD_ + lcol;
            const float* vg = vbase + (size_t)(j0 + lrow) * HD_ + lcol;
            uint32_t khp[16], klp[16], vhp[16], vlp[16];
#pragma unroll
            for (int v = 0; v < 8; v++) {
                float4 fk = *(const float4*)(kg + v * 4);
                float4 fv = *(const float4*)(vg + v * 4);
                split2(fk.x, fk.y, khp[2 * v], klp[2 * v]);
                split2(fk.z, fk.w, khp[2 * v + 1], klp[2 * v + 1]);
                split2(fv.x, fv.y, vhp[2 * v], vlp[2 * v]);
                split2(fv.z, fv.w, vhp[2 * v + 1], vlp[2 * v + 1]);
            }
            float4* dKh = (float4*)&Kh[lrow][lcol];
            float4* dKl = (float4*)&Kl[lrow][lcol];
            float4* dVh = (float4*)&Vh[lrow][lcol];
            float4* dVl = (float4*)&Vl[lrow][lcol];
#pragma unroll
            for (int i = 0; i < 4; i++) {
                dKh[i] = ((float4*)khp)[i];
                dKl[i] = ((float4*)klp)[i];
                dVh[i] = ((float4*)vhp)[i];
                dVl[i] = ((float4*)vlp)[i];
            }
        }
        __syncthreads();

        // ---- S = Q K^T ----
        float sacc[8][4];
#pragma unroll
        for (int nj = 0; nj < 8; nj++)
#pragma unroll
            for (int e = 0; e < 4; e++) sacc[nj][e] = 0.f;

#pragma unroll
        for (int ks = 0; ks < 4; ks++) {
            uint32_t bh[8][2], bl[8][2];
#pragma unroll
            for (int p = 0; p < 4; p++) {
                uint32_t off = (uint32_t)(((p * 16 + b_row) * FLDV) + ks * 16 + b_col) * 2;
                uint32_t t[4];
                ldsm_x4(t, sKh + off);
                bh[2 * p][0] = t[0]; bh[2 * p][1] = t[1];
                bh[2 * p + 1][0] = t[2]; bh[2 * p + 1][1] = t[3];
                ldsm_x4(t, sKl + off);
                bl[2 * p][0] = t[0]; bl[2 * p][1] = t[1];
                bl[2 * p + 1][0] = t[2]; bl[2 * p + 1][1] = t[3];
            }
#pragma unroll
            for (int nj = 0; nj < 8; nj++) {
                mma16816(sacc[nj], qh[ks], bh[nj]);
                mma16816(sacc[nj], ql[ks], bh[nj]);
                mma16816(sacc[nj], qh[ks], bl[nj]);
            }
        }

        // ---- online softmax ----
        float mloc[2] = {-1e30f, -1e30f};
#pragma unroll
        for (int nj = 0; nj < 8; nj++) {
            mloc[0] = fmaxf(mloc[0], fmaxf(sacc[nj][0], sacc[nj][1]));
            mloc[1] = fmaxf(mloc[1], fmaxf(sacc[nj][2], sacc[nj][3]));
        }
#pragma unroll
        for (int r = 0; r < 2; r++) {
            mloc[r] = fmaxf(mloc[r], __shfl_xor_sync(0xFFFFFFFFu, mloc[r], 1));
            mloc[r] = fmaxf(mloc[r], __shfl_xor_sync(0xFFFFFFFFu, mloc[r], 2));
        }
        float corr[2];
#pragma unroll
        for (int r = 0; r < 2; r++) {
            float mnew = fmaxf(mrun[r], mloc[r]);
            corr[r] = __expf(mrun[r] - mnew);
            mrun[r] = mnew;
        }
        float psum[2] = {0.f, 0.f};
#pragma unroll
        for (int nj = 0; nj < 8; nj++) {
            float p0 = __expf(sacc[nj][0] - mrun[0]);
            float p1 = __expf(sacc[nj][1] - mrun[0]);
            float p2 = __expf(sacc[nj][2] - mrun[1]);
            float p3 = __expf(sacc[nj][3] - mrun[1]);
            sacc[nj][0] = p0; sacc[nj][1] = p1;
            sacc[nj][2] = p2; sacc[nj][3] = p3;
            psum[0] += p0 + p1;
            psum[1] += p2 + p3;
        }
#pragma unroll
        for (int r = 0; r < 2; r++) {
            psum[r] += __shfl_xor_sync(0xFFFFFFFFu, psum[r], 1);
            psum[r] += __shfl_xor_sync(0xFFFFFFFFu, psum[r], 2);
            lrun[r] = lrun[r] * corr[r] + psum[r];
        }
#pragma unroll
        for (int dn = 0; dn < 8; dn++) {
            o[dn][0] *= corr[0]; o[dn][1] *= corr[0];
            o[dn][2] *= corr[1]; o[dn][3] *= corr[1];
        }

        // ---- repack P -> A-frags ----
        uint32_t ph[4][4], pl[4][4];
#pragma unroll
        for (int ks = 0; ks < 4; ks++) {
            const float* c0 = sacc[2 * ks];
            const float* c1 = sacc[2 * ks + 1];
            split2(c0[0], c0[1], ph[ks][0], pl[ks][0]);
            split2(c0[2], c0[3], ph[ks][1], pl[ks][1]);
            split2(c1[0], c1[1], ph[ks][2], pl[ks][2]);
            split2(c1[2], c1[3], ph[ks][3], pl[ks][3]);
        }

        // ---- O += P V ----
#pragma unroll
        for (int ks = 0; ks < 4; ks++) {
            uint32_t vbh[8][2], vbl[8][2];
#pragma unroll
            for (int p = 0; p < 4; p++) {
                uint32_t off = (uint32_t)(((ks * 16 + v_row) * FLDV) + p * 16 + v_col) * 2;
                uint32_t t[4];
                ldsm_x4_t(t, sVh + off);
                vbh[2 * p][0] = t[0]; vbh[2 * p][1] = t[1];
                vbh[2 * p + 1][0] = t[2]; vbh[2 * p + 1][1] = t[3];
                ldsm_x4_t(t, sVl + off);
                vbl[2 * p][0] = t[0]; vbl[2 * p][1] = t[1];
                vbl[2 * p + 1][0] = t[2]; vbl[2 * p + 1][1] = t[3];
            }
#pragma unroll
            for (int dn = 0; dn < 8; dn++) {
                mma16816(o[dn], ph[ks], vbh[dn]);
                mma16816(o[dn], pl[ks], vbh[dn]);
                mma16816(o[dn], ph[ks], vbl[dn]);
            }
        }
        __syncthreads();
    }

    // ---- finalize + write ctx [B,S,H] ----
    const int g  = lane >> 2;
    const int t2 = (lane & 3) * 2;
    float inv0 = 1.0f / lrun[0];
    float inv1 = 1.0f / lrun[1];
#pragma unroll
    for (int dn = 0; dn < 8; dn++) {
        int d = h * HD_ + dn * 8 + t2;
        int m0g = q0 + warp * 16 + g;
        float* dst0 = &ctx[((size_t)b * S_ + m0g) * H_ + d];
        float* dst1 = &ctx[((size_t)b * S_ + m0g + 8) * H_ + d];
        *(float2*)dst0 = make_float2(o[dn][0] * inv0, o[dn][1] * inv0);
        *(float2*)dst1 = make_float2(o[dn][2] * inv1, o[dn][3] * inv1);
    }
}

// ---------------- layernorm (one block per row) --------------------------
__global__ __launch_bounds__(256) void layernorm_k(
    const float* __restrict__ hin, const float* __restrict__ gamma,
    const float* __restrict__ beta, float* __restrict__ out)
{
    const int row = blockIdx.x;
    const int t = threadIdx.x;
    const float* hp = hin + (size_t)row * H_;
    float* op = out + (size_t)row * H_;

    float4 x4 = ((const float4*)hp)[t];
    float sum = x4.x + x4.y + x4.z + x4.w;
    float sq  = x4.x * x4.x + x4.y * x4.y + x4.z * x4.z + x4.w * x4.w;

#pragma unroll
    for (int off = 16; off > 0; off >>= 1) {
        sum += __shfl_xor_sync(0xFFFFFFFFu, sum, off);
        sq  += __shfl_xor_sync(0xFFFFFFFFu, sq,  off);
    }
    __shared__ float ssum[8], ssq[8];
    const int wid = t >> 5, lid = t & 31;
    if (lid == 0) { ssum[wid] = sum; ssq[wid] = sq; }
    __syncthreads();
    if (wid == 0) {
        float a = (lid < 8) ? ssum[lid] : 0.f;
        float b = (lid < 8) ? ssq[lid]  : 0.f;
#pragma unroll
        for (int off = 4; off > 0; off >>= 1) {
            a += __shfl_xor_sync(0xFFFFFFFFu, a, off);
            b += __shfl_xor_sync(0xFFFFFFFFu, b, off);
        }
        if (lid == 0) { ssum[0] = a; ssq[0] = b; }
    }
    __syncthreads();
    const float mean = ssum[0] * (1.0f / H_);
    const float var  = ssq[0] * (1.0f / H_) - mean * mean;
    const float rstd = rsqrtf(var + 1e-12f);

    float4 g4 = ((const float4*)gamma)[t];
    float4 b4 = ((const float4*)beta)[t];
    float4 o4;
    o4.x = g4.x * (x4.x - mean) * rstd + b4.x;
    o4.y = g4.y * (x4.y - mean) * rstd + b4.y;
    o4.z = g4.z * (x4.z - mean) * rstd + b4.z;
    o4.w = g4.w * (x4.w - mean) * rstd + b4.w;
    ((float4*)op)[t] = o4;
}

// ---------------- launch ----------------
extern "C" void kernel_launch(void* const* d_in, const int* in_sizes, int n_in,
                              void* d_out, int out_size)
{
    const float* x     = (const float*)d_in[0];
    const float* wq    = (const float*)d_in[1];
    const float* bq    = (const float*)d_in[2];
    const float* wk    = (const float*)d_in[3];
    const float* bk    = (const float*)d_in[4];
    const float* wv    = (const float*)d_in[5];
    const float* bv    = (const float*)d_in[6];
    const float* wo    = (const float*)d_in[7];
    const float* bo    = (const float*)d_in[8];
    const float* gamma = (const float*)d_in[9];
    const float* beta  = (const float*)d_in[10];

    float *q, *k, *v, *ctx, *hbuf;
    cudaGetSymbolAddress((void**)&q,    g_q);
    cudaGetSymbolAddress((void**)&k,    g_k);
    cudaGetSymbolAddress((void**)&v,    g_v);
    cudaGetSymbolAddress((void**)&ctx,  g_ctx);
    cudaGetSymbolAddress((void**)&hbuf, g_h);

    dim3 tb(256);

    // fused QKV projections (gridDim.z picks the weight set)
    gemm_bf16x3<<<dim3(H_ / BN, MTOT / BM, 3), tb>>>(
        x, wq, wk, wv, bq, bk, bv, q, k, v, nullptr, 1);

    flash_mma<<<dim3(S_ / 64, NH_, B_), 128>>>(q, k, v, ctx);

    // output projection + residual
    gemm_bf16x3<<<dim3(H_ / BN, MTOT / BM, 1), tb>>>(
        ctx, wo, wo, wo, bo, bo, bo, hbuf, hbuf, hbuf, x, 0);

    layernorm_k<<<MTOT, 256>>>(hbuf, gamma, beta, (float*)d_out);
}